// round 7
// baseline (speedup 1.0000x reference)
#include <cuda_runtime.h>
#include <cuda_bf16.h>
#include <mma.h>
#include <cstdint>
#include <cstddef>

using namespace nvcuda;

#define SCALE 0.0625f
#define EPSLN 1e-5f

// edge_tc smem byte offsets
#define OFF_A1H 0
#define OFF_A1L 33792
#define OFF_HH 67584
#define OFF_HL 101376
#define OFF_B0 135168
#define BUFSZ 40960
#define BLO 20480
#define DSMEM 217088
#define LDA 264  // bf16 elems/row, A and H tiles (64 rows)
#define LDB 40   // bf16 elems/row, B stage (256 rows x 32 k)
#define LDC 260  // f32 elems/row, C stage (aliases B at OFF_B0)

typedef wmma::fragment<wmma::matrix_a, 16, 16, 16, __nv_bfloat16, wmma::row_major> FragA;
typedef wmma::fragment<wmma::matrix_b, 16, 16, 16, __nv_bfloat16, wmma::col_major> FragB;
typedef wmma::fragment<wmma::accumulator, 16, 16, 16, float> FragC;

// ---------------- device scratch ----------------
__device__ float d_q[131072];
__device__ float d_k[131072];
__device__ float d_v[131072];
__device__ float d_an1[131072];
__device__ float d_logits[4194304];                        // [b][i][h][... ] => (bi*8+h)*256+j
__device__ unsigned short g_WeoH[65536], g_WeoL[65536];    // [256 n][256 k]
__device__ unsigned short g_We1H[262144], g_We1L[262144];  // [1024][256]
__device__ unsigned short g_We2H[262144], g_We2L[262144];  // [256][1024]

__device__ __forceinline__ void split_w(float v, unsigned short* h, unsigned short* l) {
    __nv_bfloat16 hb = __float2bfloat16(v);
    *h = __bfloat16_as_ushort(hb);
    *l = __bfloat16_as_ushort(__float2bfloat16(v - __bfloat162float(hb)));
}
__device__ __forceinline__ void split_sm(char* smp, int off, int r, int c, float v) {
    __nv_bfloat16 hb = __float2bfloat16(v);
    *(unsigned short*)(smp + off + (r * LDA + c) * 2) = __bfloat16_as_ushort(hb);
    *(unsigned short*)(smp + off + 33792 + (r * LDA + c) * 2) =
        __bfloat16_as_ushort(__float2bfloat16(v - __bfloat162float(hb)));
}
__device__ __forceinline__ unsigned smem_u32(const void* p) {
    unsigned a;
    asm("{ .reg .u64 t; cvta.to.shared.u64 t, %1; cvt.u32.u64 %0, t; }" : "=r"(a) : "l"(p));
    return a;
}
__device__ __forceinline__ void cpa16(unsigned dst, const void* src) {
    asm volatile("cp.async.ca.shared.global [%0], [%1], 16;" :: "r"(dst), "l"(src));
}
__device__ __forceinline__ void cpa_commit() { asm volatile("cp.async.commit_group;"); }
__device__ __forceinline__ void cpa_wait1() { asm volatile("cp.async.wait_group 1;"); }
__device__ __forceinline__ void cpa_wait0() { asm volatile("cp.async.wait_group 0;"); }

// ---------------- prep: edge-weight bf16 hi/lo split only ----------------
__global__ void prep_kernel(const float* __restrict__ Weo, const float* __restrict__ We1,
                            const float* __restrict__ We2) {
    int idx = blockIdx.x * 256 + threadIdx.x;  // 262144
    if (idx < 65536) split_w(Weo[idx], &g_WeoH[idx], &g_WeoL[idx]);
    split_w(We1[idx], &g_We1H[idx], &g_We1L[idx]);
    split_w(We2[idx], &g_We2H[idx], &g_We2L[idx]);
}

// ---------------- qkv projection (row-major weights, float4) ----------------
__global__ void __launch_bounds__(256) qkv_kernel(const float* __restrict__ nodes,
                                                  const float* __restrict__ conds,
                                                  const float* __restrict__ Wqkv,
                                                  const float* __restrict__ bqkv) {
    __shared__ float x[256];
    int bi = blockIdx.x, b = bi >> 8, t = threadIdx.x;
    x[t] = nodes[bi * 256 + t] + conds[(b << 8) + t];
    __syncthreads();
    const float4* x4 = (const float4*)x;
#pragma unroll
    for (int s = 0; s < 3; s++) {
        int o = t + (s << 8);
        const float4* wr = (const float4*)(Wqkv + o * 256);
        float acc = bqkv[o];
#pragma unroll 8
        for (int c = 0; c < 64; c++) {
            float4 w = wr[c], xv = x4[c];
            acc += w.x * xv.x + w.y * xv.y + w.z * xv.z + w.w * xv.w;
        }
        float* dst = (s == 0) ? d_q : (s == 1) ? d_k : d_v;
        dst[bi * 256 + t] = acc;
    }
}

// ---------------- attn: precomputed logits -> softmax -> WV -> Wno -> LN1 ----------------
__global__ void __launch_bounds__(256) attn_kernel(const float* __restrict__ nodes,
                                                   const float* __restrict__ Wno,
                                                   const float* __restrict__ bno,
                                                   const float* __restrict__ g1n,
                                                   const float* __restrict__ b1n) {
    __shared__ float lg[8 * 256];
    __shared__ float wv[256];
    __shared__ float red[20];
    int bi = blockIdx.x, b = bi >> 8, t = threadIdx.x, w = t >> 5, lane = t & 31;
    {   // load + softmax for head w
        const float* lrow = d_logits + ((size_t)bi * 8 + w) * 256;
        float m = -1e30f;
        for (int j = lane; j < 256; j += 32) {
            float v = lrow[j];
            lg[w * 256 + j] = v;
            m = fmaxf(m, v);
        }
#pragma unroll
        for (int off = 16; off; off >>= 1) m = fmaxf(m, __shfl_xor_sync(0xffffffffu, m, off));
        float s = 0.f;
        for (int j = lane; j < 256; j += 32) {
            float e = __expf(lg[w * 256 + j] - m);
            lg[w * 256 + j] = e; s += e;
        }
#pragma unroll
        for (int off = 16; off; off >>= 1) s += __shfl_xor_sync(0xffffffffu, s, off);
        float inv = 1.f / s;
        for (int j = lane; j < 256; j += 32) lg[w * 256 + j] *= inv;
    }
    __syncthreads();
    const float* vb = d_v + b * 65536;
    float acc = 0.f;
#pragma unroll 4
    for (int j = 0; j < 256; j++) acc += lg[w * 256 + j] * vb[j * 256 + t];
    wv[t] = acc;
    __syncthreads();
    float a = bno[t];
    {
        const float4* wr = (const float4*)(Wno + t * 256);
        const float4* wv4 = (const float4*)wv;
#pragma unroll 8
        for (int c = 0; c < 64; c++) {
            float4 ww = wr[c], xv = wv4[c];
            a += ww.x * xv.x + ww.y * xv.y + ww.z * xv.z + ww.w * xv.w;
        }
    }
    a += nodes[bi * 256 + t];
    float s1 = a, s2 = a * a;
#pragma unroll
    for (int off = 16; off; off >>= 1) {
        s1 += __shfl_xor_sync(0xffffffffu, s1, off);
        s2 += __shfl_xor_sync(0xffffffffu, s2, off);
    }
    if (lane == 0) { red[w] = s1; red[8 + w] = s2; }
    __syncthreads();
    if (t == 0) {
        float a1 = 0.f, a2 = 0.f;
        for (int x = 0; x < 8; x++) { a1 += red[x]; a2 += red[8 + x]; }
        float m = a1 * (1.f / 256.f);
        red[16] = m;
        red[17] = rsqrtf(a2 * (1.f / 256.f) - m * m + EPSLN);
    }
    __syncthreads();
    d_an1[bi * 256 + t] = (a - red[16]) * red[17] * g1n[t] + b1n[t];
}

// ---------------- node MLP (row-major weights, float4) ----------------
__global__ void __launch_bounds__(256) nodemlp_kernel(const float* __restrict__ Wn1,
                                                      const float* __restrict__ bn1,
                                                      const float* __restrict__ Wn2,
                                                      const float* __restrict__ bn2,
                                                      const float* __restrict__ g2n,
                                                      const float* __restrict__ b2n,
                                                      float* __restrict__ out_nodes) {
    __shared__ float a[256];
    __shared__ float h[1024];
    __shared__ float red[20];
    int bi = blockIdx.x, t = threadIdx.x, w = t >> 5, lane = t & 31;
    a[t] = d_an1[bi * 256 + t];
    __syncthreads();
    const float4* a4 = (const float4*)a;
#pragma unroll
    for (int s = 0; s < 4; s++) {
        int m = t + (s << 8);
        const float4* wr = (const float4*)(Wn1 + m * 256);
        float acc = bn1[m];
#pragma unroll 8
        for (int c = 0; c < 64; c++) {
            float4 ww = wr[c], xv = a4[c];
            acc += ww.x * xv.x + ww.y * xv.y + ww.z * xv.z + ww.w * xv.w;
        }
        h[m] = fmaxf(acc, 0.f);
    }
    __syncthreads();
    float o = bn2[t];
    {
        const float4* wr = (const float4*)(Wn2 + t * 1024);
        const float4* h4 = (const float4*)h;
#pragma unroll 8
        for (int c = 0; c < 256; c++) {
            float4 ww = wr[c], xv = h4[c];
            o += ww.x * xv.x + ww.y * xv.y + ww.z * xv.z + ww.w * xv.w;
        }
    }
    float v = o + a[t];
    float s1 = v, s2 = v * v;
#pragma unroll
    for (int off = 16; off; off >>= 1) {
        s1 += __shfl_xor_sync(0xffffffffu, s1, off);
        s2 += __shfl_xor_sync(0xffffffffu, s2, off);
    }
    if (lane == 0) { red[w] = s1; red[8 + w] = s2; }
    __syncthreads();
    if (t == 0) {
        float a1 = 0.f, a2 = 0.f;
        for (int x = 0; x < 8; x++) { a1 += red[x]; a2 += red[8 + x]; }
        float m = a1 * (1.f / 256.f);
        red[16] = m;
        red[17] = rsqrtf(a2 * (1.f / 256.f) - m * m + EPSLN);
    }
    __syncthreads();
    out_nodes[bi * 256 + t] = (v - red[16]) * red[17] * g2n[t] + b2n[t];
}

// ---------------- edge pipeline: split-bf16 WMMA + cp.async double-buffered B ----------------
__device__ __forceinline__ void stage32(unsigned sb, int buf, const unsigned short* __restrict__ WH,
                                        const unsigned short* __restrict__ WL, int wp, int k0,
                                        int t) {
    unsigned dH = sb + OFF_B0 + buf * BUFSZ + t * 80;
    unsigned dL = dH + BLO;
    const unsigned short* sH = WH + (size_t)t * wp + k0;
    const unsigned short* sL = WL + (size_t)t * wp + k0;
#pragma unroll
    for (int s = 0; s < 4; s++) {
        cpa16(dH + s * 16, sH + s * 8);
        cpa16(dL + s * 16, sL + s * 8);
    }
    cpa_commit();
}

__device__ __forceinline__ void mma32(const char* smp, int aoff, int boff, FragC acc[2][4],
                                      int mg, int ng, int acol0) {
    const __nv_bfloat16* Ahi = (const __nv_bfloat16*)(smp + aoff);
    const __nv_bfloat16* Alo = (const __nv_bfloat16*)(smp + aoff + 33792);
    const __nv_bfloat16* Bhi = (const __nv_bfloat16*)(smp + boff);
    const __nv_bfloat16* Blo = (const __nv_bfloat16*)(smp + boff + BLO);
#pragma unroll
    for (int ks = 0; ks < 2; ks++) {
        int col = acol0 + ks * 16;
        FragA ah[2], al[2];
#pragma unroll
        for (int mi = 0; mi < 2; mi++) {
            int row0 = mg * 32 + mi * 16;
            wmma::load_matrix_sync(ah[mi], Ahi + row0 * LDA + col, LDA);
            wmma::load_matrix_sync(al[mi], Alo + row0 * LDA + col, LDA);
        }
#pragma unroll
        for (int ns = 0; ns < 4; ns++) {
            int n0 = ng * 64 + ns * 16;
            FragB bh, bl;
            wmma::load_matrix_sync(bh, Bhi + n0 * LDB + ks * 16, LDB);
            wmma::load_matrix_sync(bl, Blo + n0 * LDB + ks * 16, LDB);
#pragma unroll
            for (int mi = 0; mi < 2; mi++) {
                wmma::mma_sync(acc[mi][ns], ah[mi], bh, acc[mi][ns]);
                wmma::mma_sync(acc[mi][ns], ah[mi], bl, acc[mi][ns]);
                wmma::mma_sync(acc[mi][ns], al[mi], bh, acc[mi][ns]);
            }
        }
    }
}

// full 256-k GEMM: 8 chunks of 32 k, double-buffered cp.async staging
__device__ __forceinline__ void run_gemm(char* smp, unsigned sb,
                                         const unsigned short* __restrict__ WH,
                                         const unsigned short* __restrict__ WL, int wp,
                                         int kglob0, int aoff, FragC acc[2][4], int mg, int ng,
                                         int t) {
    stage32(sb, 0, WH, WL, wp, kglob0, t);
#pragma unroll 1
    for (int c = 0; c < 8; c++) {
        if (c < 7) stage32(sb, (c + 1) & 1, WH, WL, wp, kglob0 + (c + 1) * 32, t);
        if (c < 7) cpa_wait1(); else cpa_wait0();
        __syncthreads();
        mma32(smp, aoff, OFF_B0 + (c & 1) * BUFSZ, acc, mg, ng, c * 32);
        __syncthreads();
    }
}

__device__ __forceinline__ void storeC(char* smp, FragC acc[2][4], int mg, int ng) {
    float* C = (float*)(smp + OFF_B0);
#pragma unroll
    for (int mi = 0; mi < 2; mi++)
#pragma unroll
        for (int ns = 0; ns < 4; ns++)
            wmma::store_matrix_sync(C + (mg * 32 + mi * 16) * LDC + ng * 64 + ns * 16,
                                    acc[mi][ns], LDC, wmma::mem_row_major);
}

__global__ void __launch_bounds__(256) edge_tc(const float* __restrict__ edges,
                                               const float* __restrict__ beo,
                                               const float* __restrict__ g1e,
                                               const float* __restrict__ b1e,
                                               const float* __restrict__ be1,
                                               const float* __restrict__ be2,
                                               const float* __restrict__ g2e,
                                               const float* __restrict__ b2e,
                                               float* __restrict__ out_edges) {
    extern __shared__ char smp[];
    const unsigned sb = smem_u32(smp);
    const int t = threadIdx.x, w = t >> 5, lane = t & 31;
    const int mg = w >> 1, ng = w & 1;     // wait: need mg 0..3 over 64 rows (4x16? no 2x(2x16)=...)
    const int blk = blockIdx.x;            // 0..2047, 64 rows each
    const int bi = blk >> 2;
    const int b = bi >> 8;
    const int j0 = (blk & 3) << 6;
    const size_t rowbase = (size_t)blk * 64;
    const int r = t >> 2, sub = t & 3;     // epilogue: 4 threads per row
    float* Cst = (float*)(smp + OFF_B0);

    // warp tiling over 64 rows x 256 cols: mg in 0..1 (32 rows), ng in 0..3 (64 cols)
    const int MG = w >> 2, NG = w & 3;

    // ---- T = q*k*scale + e -> split A1 tiles; fused per-head logits ----
    {
        float qv = d_q[bi * 256 + t] * SCALE;
        const float* ebase = edges + rowbase * 256 + t;
        const float* kbase = d_k + ((size_t)(b << 8) + j0) * 256 + t;
        float* lbase = d_logits + ((size_t)bi * 8 + w) * 256 + j0;
#pragma unroll 4
        for (int i = 0; i < 64; i++) {
            float v = qv * kbase[i * 256] + ebase[i * 256];
            split_sm(smp, OFF_A1H, i, t, v);
            float s = v;
#pragma unroll
            for (int off = 16; off; off >>= 1) s += __shfl_xor_sync(0xffffffffu, s, off);
            if (lane == 0) lbase[i] = s;
        }
    }
    // no sync needed before staging; run_gemm syncs before first MMA

    // ---- G1: C = T @ Weo^T ----
    FragC acc1[2][4];
#pragma unroll
    for (int mi = 0; mi < 2; mi++)
#pragma unroll
        for (int ns = 0; ns < 4; ns++) wmma::fill_fragment(acc1[mi][ns], 0.f);
    run_gemm(smp, sb, g_WeoH, g_WeoL, 256, 0, OFF_A1H, acc1, MG, NG, t);
    storeC(smp, acc1, MG, NG);
    __syncthreads();

    // ---- Epi1: v = relu(C+beo)+e ; LN -> A1 ----
    {
        float s1 = 0.f, s2 = 0.f;
        const float* erow = edges + (rowbase + r) * 256;
        float* Crow = Cst + r * LDC;
#pragma unroll 4
        for (int i = 0; i < 64; i++) {
            int c = sub * 64 + i;
            float v = fmaxf(Crow[c] + beo[c], 0.f) + erow[c];
            Crow[c] = v; s1 += v; s2 += v * v;
        }
        s1 += __shfl_xor_sync(0xffffffffu, s1, 1); s2 += __shfl_xor_sync(0xffffffffu, s2, 1);
        s1 += __shfl_xor_sync(0xffffffffu, s1, 2); s2 += __shfl_xor_sync(0xffffffffu, s2, 2);
        float m = s1 * (1.f / 256.f);
        float rs = rsqrtf(s2 * (1.f / 256.f) - m * m + EPSLN);
#pragma unroll 4
        for (int i = 0; i < 64; i++) {
            int c = sub * 64 + i;
            split_sm(smp, OFF_A1H, r, c, (Crow[c] - m) * rs * g1e[c] + b1e[c]);
        }
    }
    __syncthreads();

    // ---- MLP: 4 hidden chunks: G2 -> relu -> G3 accumulate ----
    FragC acc3[2][4];
#pragma unroll
    for (int mi = 0; mi < 2; mi++)
#pragma unroll
        for (int ns = 0; ns < 4; ns++) wmma::fill_fragment(acc3[mi][ns], 0.f);

#pragma unroll 1
    for (int nc = 0; nc < 4; nc++) {
        FragC acc2[2][4];
#pragma unroll
        for (int mi = 0; mi < 2; mi++)
#pragma unroll
            for (int ns = 0; ns < 4; ns++) wmma::fill_fragment(acc2[mi][ns], 0.f);
        run_gemm(smp, sb, g_We1H + nc * 65536, g_We1L + nc * 65536, 256, 0, OFF_A1H, acc2,
                 MG, NG, t);
        storeC(smp, acc2, MG, NG);
        __syncthreads();
        {   // Epi-H: H = relu(C + be1)
            float* Crow = Cst + r * LDC;
#pragma unroll 4
            for (int i = 0; i < 64; i++) {
                int c = sub * 64 + i;
                split_sm(smp, OFF_HH, r, c, fmaxf(Crow[c] + be1[nc * 256 + c], 0.f));
            }
        }
        __syncthreads();
        run_gemm(smp, sb, g_We2H, g_We2L, 1024, nc * 256, OFF_HH, acc3, MG, NG, t);
    }
    storeC(smp, acc3, MG, NG);
    __syncthreads();

    // ---- Epi3: v = C + be2 + A1 ; LN -> out ----
    {
        float s1 = 0.f, s2 = 0.f;
        float* Crow = Cst + r * LDC;
        const unsigned short* a1h = (const unsigned short*)(smp + OFF_A1H) + r * LDA;
        const unsigned short* a1l = (const unsigned short*)(smp + OFF_A1L) + r * LDA;
#pragma unroll 4
        for (int i = 0; i < 64; i++) {
            int c = sub * 64 + i;
            float a1 = __bfloat162float(__ushort_as_bfloat16(a1h[c])) +
                       __bfloat162float(__ushort_as_bfloat16(a1l[c]));
            float v = Crow[c] + be2[c] + a1;
            Crow[c] = v; s1 += v; s2 += v * v;
        }
        s1 += __shfl_xor_sync(0xffffffffu, s1, 1); s2 += __shfl_xor_sync(0xffffffffu, s2, 1);
        s1 += __shfl_xor_sync(0xffffffffu, s1, 2); s2 += __shfl_xor_sync(0xffffffffu, s2, 2);
        float m = s1 * (1.f / 256.f);
        float rs = rsqrtf(s2 * (1.f / 256.f) - m * m + EPSLN);
        float* orow = out_edges + (rowbase + r) * 256;
#pragma unroll 4
        for (int i = 0; i < 64; i++) {
            int c = sub * 64 + i;
            orow[c] = (Crow[c] - m) * rs * g2e[c] + b2e[c];
        }
    }
}

__global__ void copy_conds(const float* __restrict__ conds, float* __restrict__ dst) {
    int t = blockIdx.x * 256 + threadIdx.x;
    if (t < 512) dst[t] = conds[t];
}

// ---------------- launch ----------------
extern "C" void kernel_launch(void* const* d_in, const int* in_sizes, int n_in,
                              void* d_out, int out_size) {
    const float* nodes = (const float*)d_in[0];
    const float* edges = (const float*)d_in[1];
    const float* conds = (const float*)d_in[2];
    const float* Wqkv = (const float*)d_in[3];
    const float* bqkv = (const float*)d_in[4];
    const float* Wno = (const float*)d_in[5];
    const float* bno = (const float*)d_in[6];
    const float* Weo = (const float*)d_in[7];
    const float* beo = (const float*)d_in[8];
    const float* g1n = (const float*)d_in[9];
    const float* b1n = (const float*)d_in[10];
    const float* g1e = (const float*)d_in[11];
    const float* b1e = (const float*)d_in[12];
    const float* Wn1 = (const float*)d_in[13];
    const float* bn1 = (const float*)d_in[14];
    const float* Wn2 = (const float*)d_in[15];
    const float* bn2 = (const float*)d_in[16];
    const float* We1 = (const float*)d_in[17];
    const float* be1 = (const float*)d_in[18];
    const float* We2 = (const float*)d_in[19];
    const float* be2 = (const float*)d_in[20];
    const float* g2n = (const float*)d_in[21];
    const float* b2n = (const float*)d_in[22];
    const float* g2e = (const float*)d_in[23];
    const float* b2e = (const float*)d_in[24];

    float* out = (float*)d_out;
    float* out_nodes = out;
    float* out_edges = out + 131072;
    float* out_conds = out + 131072 + 33554432;

    cudaFuncSetAttribute(edge_tc, cudaFuncAttributeMaxDynamicSharedMemorySize, DSMEM);

    prep_kernel<<<1024, 256>>>(Weo, We1, We2);
    qkv_kernel<<<512, 256>>>(nodes, conds, Wqkv, bqkv);
    edge_tc<<<2048, 256, DSMEM>>>(edges, beo, g1e, b1e, be1, be2, g2e, b2e, out_edges);
    attn_kernel<<<512, 256>>>(nodes, Wno, bno, g1n, b1n);
    nodemlp_kernel<<<512, 256>>>(Wn1, bn1, Wn2, bn2, g2n, b2n, out_nodes);
    copy_conds<<<2, 256>>>(conds, out_conds);
}

// round 8
// speedup vs baseline: 1.2923x; 1.2923x over previous
#include <cuda_runtime.h>
#include <cuda_bf16.h>
#include <mma.h>
#include <cstdint>
#include <cstddef>

using namespace nvcuda;

#define SCALE 0.0625f
#define EPSLN 1e-5f

// edge_tc smem byte offsets
#define OFF_A1H 0
#define OFF_A1L 33792
#define OFF_HH 67584
#define OFF_HL 101376
#define OFF_B0 135168
#define BUFSZ 40960
#define BLO 20480
#define DSMEM 217088
#define LDA 264  // bf16 elems/row, A and H tiles (64 rows)
#define LDB 40   // bf16 elems/row, B stage (256 rows x 32 k)
#define LDC 260  // f32 elems/row, C stage (aliases B at OFF_B0)

typedef wmma::fragment<wmma::matrix_a, 16, 16, 16, __nv_bfloat16, wmma::row_major> FragA;
typedef wmma::fragment<wmma::matrix_b, 16, 16, 16, __nv_bfloat16, wmma::col_major> FragB;
typedef wmma::fragment<wmma::accumulator, 16, 16, 16, float> FragC;

// ---------------- device scratch ----------------
__device__ float d_q[131072];
__device__ float d_k[131072];
__device__ float d_v[131072];
__device__ float d_an1[131072];
__device__ float d_logits[1048576];  // (bi*8+h)*256 + j
// chunk-major packed weights: [kchunk][rows 256][k 32]
__device__ unsigned short g_WeoH[65536], g_WeoL[65536];    // 8 chunks
__device__ unsigned short g_We1H[262144], g_We1L[262144];  // 4 nc x 8 chunks
__device__ unsigned short g_We2H[262144], g_We2L[262144];  // 32 chunks (8 per nc)

__device__ __forceinline__ void split_w(float v, unsigned short* h, unsigned short* l) {
    __nv_bfloat16 hb = __float2bfloat16(v);
    *h = __bfloat16_as_ushort(hb);
    *l = __bfloat16_as_ushort(__float2bfloat16(v - __bfloat162float(hb)));
}
__device__ __forceinline__ void split_sm(char* smp, int off, int r, int c, float v) {
    __nv_bfloat16 hb = __float2bfloat16(v);
    *(unsigned short*)(smp + off + (r * LDA + c) * 2) = __bfloat16_as_ushort(hb);
    *(unsigned short*)(smp + off + 33792 + (r * LDA + c) * 2) =
        __bfloat16_as_ushort(__float2bfloat16(v - __bfloat162float(hb)));
}
__device__ __forceinline__ unsigned smem_u32(const void* p) {
    unsigned a;
    asm("{ .reg .u64 t; cvta.to.shared.u64 t, %1; cvt.u32.u64 %0, t; }" : "=r"(a) : "l"(p));
    return a;
}
__device__ __forceinline__ void cpa16(unsigned dst, const void* src) {
    asm volatile("cp.async.ca.shared.global [%0], [%1], 16;" :: "r"(dst), "l"(src));
}
__device__ __forceinline__ void cpa_commit() { asm volatile("cp.async.commit_group;"); }
__device__ __forceinline__ void cpa_wait1() { asm volatile("cp.async.wait_group 1;"); }
__device__ __forceinline__ void cpa_wait0() { asm volatile("cp.async.wait_group 0;"); }

// ---------------- prep: split + chunk-major pack of edge weights ----------------
__global__ void prep_kernel(const float* __restrict__ Weo, const float* __restrict__ We1,
                            const float* __restrict__ We2) {
    int idx = blockIdx.x * 256 + threadIdx.x;  // 262144
    if (idx < 65536) {  // Weo [256 n][256 k]
        int n = idx >> 8, k = idx & 255;
        int kc = k >> 5, kk = k & 31;
        int dst = kc * 8192 + n * 32 + kk;
        split_w(Weo[idx], &g_WeoH[dst], &g_WeoL[dst]);
    }
    {   // We1 [1024 m][256 k] -> [(nc*8+kc)][row=m&255][kk]
        int m = idx >> 8, k = idx & 255;
        int dst = ((m >> 8) * 8 + (k >> 5)) * 8192 + (m & 255) * 32 + (k & 31);
        split_w(We1[idx], &g_We1H[dst], &g_We1L[dst]);
    }
    {   // We2 [256 n][1024 k] -> [kc 0..31][n][kk]
        int n = idx >> 10, k = idx & 1023;
        int dst = (k >> 5) * 8192 + n * 32 + (k & 31);
        split_w(We2[idx], &g_We2H[dst], &g_We2L[dst]);
    }
}

// ---------------- qkv projection (row-major weights, float4) ----------------
__global__ void __launch_bounds__(256) qkv_kernel(const float* __restrict__ nodes,
                                                  const float* __restrict__ conds,
                                                  const float* __restrict__ Wqkv,
                                                  const float* __restrict__ bqkv) {
    __shared__ float x[256];
    int bi = blockIdx.x, b = bi >> 8, t = threadIdx.x;
    x[t] = nodes[bi * 256 + t] + conds[(b << 8) + t];
    __syncthreads();
    const float4* x4 = (const float4*)x;
#pragma unroll
    for (int s = 0; s < 3; s++) {
        int o = t + (s << 8);
        const float4* wr = (const float4*)(Wqkv + o * 256);
        float acc = bqkv[o];
#pragma unroll 8
        for (int c = 0; c < 64; c++) {
            float4 w = wr[c], xv = x4[c];
            acc += w.x * xv.x + w.y * xv.y + w.z * xv.z + w.w * xv.w;
        }
        float* dst = (s == 0) ? d_q : (s == 1) ? d_k : d_v;
        dst[bi * 256 + t] = acc;
    }
}

// ---------------- attn: precomputed logits -> softmax -> WV -> Wno -> LN1 ----------------
__global__ void __launch_bounds__(256) attn_kernel(const float* __restrict__ nodes,
                                                   const float* __restrict__ Wno,
                                                   const float* __restrict__ bno,
                                                   const float* __restrict__ g1n,
                                                   const float* __restrict__ b1n) {
    __shared__ float lg[8 * 256];
    __shared__ float wv[256];
    __shared__ float red[20];
    int bi = blockIdx.x, b = bi >> 8, t = threadIdx.x, w = t >> 5, lane = t & 31;
    {
        const float* lrow = d_logits + ((size_t)bi * 8 + w) * 256;
        float m = -1e30f;
        for (int j = lane; j < 256; j += 32) {
            float v = lrow[j];
            lg[w * 256 + j] = v;
            m = fmaxf(m, v);
        }
#pragma unroll
        for (int off = 16; off; off >>= 1) m = fmaxf(m, __shfl_xor_sync(0xffffffffu, m, off));
        float s = 0.f;
        for (int j = lane; j < 256; j += 32) {
            float e = __expf(lg[w * 256 + j] - m);
            lg[w * 256 + j] = e; s += e;
        }
#pragma unroll
        for (int off = 16; off; off >>= 1) s += __shfl_xor_sync(0xffffffffu, s, off);
        float inv = 1.f / s;
        for (int j = lane; j < 256; j += 32) lg[w * 256 + j] *= inv;
    }
    __syncthreads();
    const float* vb = d_v + b * 65536;
    float acc = 0.f;
#pragma unroll 4
    for (int j = 0; j < 256; j++) acc += lg[w * 256 + j] * vb[j * 256 + t];
    wv[t] = acc;
    __syncthreads();
    float a = bno[t];
    {
        const float4* wr = (const float4*)(Wno + t * 256);
        const float4* wv4 = (const float4*)wv;
#pragma unroll 8
        for (int c = 0; c < 64; c++) {
            float4 ww = wr[c], xv = wv4[c];
            a += ww.x * xv.x + ww.y * xv.y + ww.z * xv.z + ww.w * xv.w;
        }
    }
    a += nodes[bi * 256 + t];
    float s1 = a, s2 = a * a;
#pragma unroll
    for (int off = 16; off; off >>= 1) {
        s1 += __shfl_xor_sync(0xffffffffu, s1, off);
        s2 += __shfl_xor_sync(0xffffffffu, s2, off);
    }
    if (lane == 0) { red[w] = s1; red[8 + w] = s2; }
    __syncthreads();
    if (t == 0) {
        float a1 = 0.f, a2 = 0.f;
        for (int x = 0; x < 8; x++) { a1 += red[x]; a2 += red[8 + x]; }
        float m = a1 * (1.f / 256.f);
        red[16] = m;
        red[17] = rsqrtf(a2 * (1.f / 256.f) - m * m + EPSLN);
    }
    __syncthreads();
    d_an1[bi * 256 + t] = (a - red[16]) * red[17] * g1n[t] + b1n[t];
}

// ---------------- node MLP (row-major weights, float4) ----------------
__global__ void __launch_bounds__(256) nodemlp_kernel(const float* __restrict__ Wn1,
                                                      const float* __restrict__ bn1,
                                                      const float* __restrict__ Wn2,
                                                      const float* __restrict__ bn2,
                                                      const float* __restrict__ g2n,
                                                      const float* __restrict__ b2n,
                                                      float* __restrict__ out_nodes) {
    __shared__ float a[256];
    __shared__ float h[1024];
    __shared__ float red[20];
    int bi = blockIdx.x, t = threadIdx.x, w = t >> 5, lane = t & 31;
    a[t] = d_an1[bi * 256 + t];
    __syncthreads();
    const float4* a4 = (const float4*)a;
#pragma unroll
    for (int s = 0; s < 4; s++) {
        int m = t + (s << 8);
        const float4* wr = (const float4*)(Wn1 + m * 256);
        float acc = bn1[m];
#pragma unroll 8
        for (int c = 0; c < 64; c++) {
            float4 ww = wr[c], xv = a4[c];
            acc += ww.x * xv.x + ww.y * xv.y + ww.z * xv.z + ww.w * xv.w;
        }
        h[m] = fmaxf(acc, 0.f);
    }
    __syncthreads();
    float o = bn2[t];
    {
        const float4* wr = (const float4*)(Wn2 + t * 1024);
        const float4* h4 = (const float4*)h;
#pragma unroll 8
        for (int c = 0; c < 256; c++) {
            float4 ww = wr[c], xv = h4[c];
            o += ww.x * xv.x + ww.y * xv.y + ww.z * xv.z + ww.w * xv.w;
        }
    }
    float v = o + a[t];
    float s1 = v, s2 = v * v;
#pragma unroll
    for (int off = 16; off; off >>= 1) {
        s1 += __shfl_xor_sync(0xffffffffu, s1, off);
        s2 += __shfl_xor_sync(0xffffffffu, s2, off);
    }
    if (lane == 0) { red[w] = s1; red[8 + w] = s2; }
    __syncthreads();
    if (t == 0) {
        float a1 = 0.f, a2 = 0.f;
        for (int x = 0; x < 8; x++) { a1 += red[x]; a2 += red[8 + x]; }
        float m = a1 * (1.f / 256.f);
        red[16] = m;
        red[17] = rsqrtf(a2 * (1.f / 256.f) - m * m + EPSLN);
    }
    __syncthreads();
    out_nodes[bi * 256 + t] = (v - red[16]) * red[17] * g2n[t] + b2n[t];
}

// ---------------- edge pipeline: split-bf16 WMMA + coalesced cp.async staging ----------------
// One 32-k chunk (tile = 8192 ushort = 16KB) staged contiguously; thread t owns row t.
__device__ __forceinline__ void stage32(unsigned sb, int buf,
                                        const unsigned short* __restrict__ WH,
                                        const unsigned short* __restrict__ WL, int chunk,
                                        int t) {
    unsigned dH = sb + OFF_B0 + buf * BUFSZ + t * 80;
    const unsigned short* sH = WH + chunk * 8192 + t * 32;
    const unsigned short* sL = WL + chunk * 8192 + t * 32;
#pragma unroll
    for (int s = 0; s < 4; s++) {
        cpa16(dH + s * 16, sH + s * 8);
        cpa16(dH + BLO + s * 16, sL + s * 8);
    }
    cpa_commit();
}

__device__ __forceinline__ void mma32(const char* smp, int aoff, int boff, FragC acc[2][4],
                                      int mg, int ng, int acol0) {
    const __nv_bfloat16* Ahi = (const __nv_bfloat16*)(smp + aoff);
    const __nv_bfloat16* Alo = (const __nv_bfloat16*)(smp + aoff + 33792);
    const __nv_bfloat16* Bhi = (const __nv_bfloat16*)(smp + boff);
    const __nv_bfloat16* Blo = (const __nv_bfloat16*)(smp + boff + BLO);
#pragma unroll
    for (int ks = 0; ks < 2; ks++) {
        int col = acol0 + ks * 16;
        FragA ah[2], al[2];
#pragma unroll
        for (int mi = 0; mi < 2; mi++) {
            int row0 = mg * 32 + mi * 16;
            wmma::load_matrix_sync(ah[mi], Ahi + row0 * LDA + col, LDA);
            wmma::load_matrix_sync(al[mi], Alo + row0 * LDA + col, LDA);
        }
#pragma unroll
        for (int ns = 0; ns < 4; ns++) {
            int n0 = ng * 64 + ns * 16;
            FragB bh, bl;
            wmma::load_matrix_sync(bh, Bhi + n0 * LDB + ks * 16, LDB);
            wmma::load_matrix_sync(bl, Blo + n0 * LDB + ks * 16, LDB);
#pragma unroll
            for (int mi = 0; mi < 2; mi++) {
                wmma::mma_sync(acc[mi][ns], ah[mi], bh, acc[mi][ns]);
                wmma::mma_sync(acc[mi][ns], ah[mi], bl, acc[mi][ns]);
                wmma::mma_sync(acc[mi][ns], al[mi], bh, acc[mi][ns]);
            }
        }
    }
}

// full 256-k GEMM: 8 chunks of 32 k, double-buffered contiguous staging
__device__ __forceinline__ void run_gemm(char* smp, unsigned sb,
                                         const unsigned short* __restrict__ WH,
                                         const unsigned short* __restrict__ WL, int aoff,
                                         FragC acc[2][4], int mg, int ng, int t) {
    stage32(sb, 0, WH, WL, 0, t);
#pragma unroll 1
    for (int c = 0; c < 8; c++) {
        if (c < 7) stage32(sb, (c + 1) & 1, WH, WL, c + 1, t);
        if (c < 7) cpa_wait1(); else cpa_wait0();
        __syncthreads();
        mma32(smp, aoff, OFF_B0 + (c & 1) * BUFSZ, acc, mg, ng, c * 32);
        __syncthreads();
    }
}

__device__ __forceinline__ void storeC(char* smp, FragC acc[2][4], int mg, int ng) {
    float* C = (float*)(smp + OFF_B0);
#pragma unroll
    for (int mi = 0; mi < 2; mi++)
#pragma unroll
        for (int ns = 0; ns < 4; ns++)
            wmma::store_matrix_sync(C + (mg * 32 + mi * 16) * LDC + ng * 64 + ns * 16,
                                    acc[mi][ns], LDC, wmma::mem_row_major);
}

__global__ void __launch_bounds__(256) edge_tc(const float* __restrict__ edges,
                                               const float* __restrict__ beo,
                                               const float* __restrict__ g1e,
                                               const float* __restrict__ b1e,
                                               const float* __restrict__ be1,
                                               const float* __restrict__ be2,
                                               const float* __restrict__ g2e,
                                               const float* __restrict__ b2e,
                                               float* __restrict__ out_edges) {
    extern __shared__ char smp[];
    const unsigned sb = smem_u32(smp);
    const int t = threadIdx.x, w = t >> 5, lane = t & 31;
    const int blk = blockIdx.x;   // 0..2047, 64 edge rows each
    const int bi = blk >> 2;
    const int b = bi >> 8;
    const int j0 = (blk & 3) << 6;
    const size_t rowbase = (size_t)blk * 64;
    const int r = t >> 2, sub = t & 3;  // epilogue: 4 threads per row
    const int MG = w >> 2, NG = w & 3;  // warp tile: 32 rows x 64 cols
    float* Cst = (float*)(smp + OFF_B0);

    // ---- T = q*k*scale + e -> split A1 tiles; fused per-head logits ----
    {
        float qv = d_q[bi * 256 + t] * SCALE;
        const float* ebase = edges + rowbase * 256 + t;
        const float* kbase = d_k + ((size_t)(b << 8) + j0) * 256 + t;
        float* lbase = d_logits + ((size_t)bi * 8 + w) * 256 + j0;
#pragma unroll 4
        for (int i = 0; i < 64; i++) {
            float v = qv * kbase[i * 256] + ebase[i * 256];
            split_sm(smp, OFF_A1H, i, t, v);
            float s = v;
#pragma unroll
            for (int off = 16; off; off >>= 1) s += __shfl_xor_sync(0xffffffffu, s, off);
            if (lane == 0) lbase[i] = s;
        }
    }

    // ---- G1: C = T @ Weo^T ----
    FragC acc1[2][4];
#pragma unroll
    for (int mi = 0; mi < 2; mi++)
#pragma unroll
        for (int ns = 0; ns < 4; ns++) wmma::fill_fragment(acc1[mi][ns], 0.f);
    run_gemm(smp, sb, g_WeoH, g_WeoL, OFF_A1H, acc1, MG, NG, t);
    storeC(smp, acc1, MG, NG);
    __syncthreads();

    // ---- Epi1: v = relu(C+beo)+e ; LN -> A1 ----
    {
        float s1 = 0.f, s2 = 0.f;
        const float* erow = edges + (rowbase + r) * 256;
        float* Crow = Cst + r * LDC;
#pragma unroll 4
        for (int i = 0; i < 64; i++) {
            int c = sub * 64 + i;
            float v = fmaxf(Crow[c] + beo[c], 0.f) + erow[c];
            Crow[c] = v; s1 += v; s2 += v * v;
        }
        s1 += __shfl_xor_sync(0xffffffffu, s1, 1); s2 += __shfl_xor_sync(0xffffffffu, s2, 1);
        s1 += __shfl_xor_sync(0xffffffffu, s1, 2); s2 += __shfl_xor_sync(0xffffffffu, s2, 2);
        float m = s1 * (1.f / 256.f);
        float rs = rsqrtf(s2 * (1.f / 256.f) - m * m + EPSLN);
#pragma unroll 4
        for (int i = 0; i < 64; i++) {
            int c = sub * 64 + i;
            split_sm(smp, OFF_A1H, r, c, (Crow[c] - m) * rs * g1e[c] + b1e[c]);
        }
    }
    __syncthreads();

    // ---- MLP: 4 hidden chunks: G2 -> relu -> G3 accumulate ----
    FragC acc3[2][4];
#pragma unroll
    for (int mi = 0; mi < 2; mi++)
#pragma unroll
        for (int ns = 0; ns < 4; ns++) wmma::fill_fragment(acc3[mi][ns], 0.f);

#pragma unroll 1
    for (int nc = 0; nc < 4; nc++) {
        FragC acc2[2][4];
#pragma unroll
        for (int mi = 0; mi < 2; mi++)
#pragma unroll
            for (int ns = 0; ns < 4; ns++) wmma::fill_fragment(acc2[mi][ns], 0.f);
        run_gemm(smp, sb, g_We1H + nc * 65536, g_We1L + nc * 65536, OFF_A1H, acc2, MG, NG, t);
        storeC(smp, acc2, MG, NG);
        __syncthreads();
        {   // Epi-H: H = relu(C + be1)
            float* Crow = Cst + r * LDC;
#pragma unroll 4
            for (int i = 0; i < 64; i++) {
                int c = sub * 64 + i;
                split_sm(smp, OFF_HH, r, c, fmaxf(Crow[c] + be1[nc * 256 + c], 0.f));
            }
        }
        __syncthreads();
        run_gemm(smp, sb, g_We2H + nc * 65536, g_We2L + nc * 65536, OFF_HH, acc3, MG, NG, t);
    }
    storeC(smp, acc3, MG, NG);
    __syncthreads();

    // ---- Epi3: v = C + be2 + A1 ; LN -> out ----
    {
        float s1 = 0.f, s2 = 0.f;
        float* Crow = Cst + r * LDC;
        const unsigned short* a1h = (const unsigned short*)(smp + OFF_A1H) + r * LDA;
        const unsigned short* a1l = (const unsigned short*)(smp + OFF_A1L) + r * LDA;
#pragma unroll 4
        for (int i = 0; i < 64; i++) {
            int c = sub * 64 + i;
            float a1 = __bfloat162float(__ushort_as_bfloat16(a1h[c])) +
                       __bfloat162float(__ushort_as_bfloat16(a1l[c]));
            float v = Crow[c] + be2[c] + a1;
            Crow[c] = v; s1 += v; s2 += v * v;
        }
        s1 += __shfl_xor_sync(0xffffffffu, s1, 1); s2 += __shfl_xor_sync(0xffffffffu, s2, 1);
        s1 += __shfl_xor_sync(0xffffffffu, s1, 2); s2 += __shfl_xor_sync(0xffffffffu, s2, 2);
        float m = s1 * (1.f / 256.f);
        float rs = rsqrtf(s2 * (1.f / 256.f) - m * m + EPSLN);
        float* orow = out_edges + (rowbase + r) * 256;
#pragma unroll 4
        for (int i = 0; i < 64; i++) {
            int c = sub * 64 + i;
            orow[c] = (Crow[c] - m) * rs * g2e[c] + b2e[c];
        }
    }
}

__global__ void copy_conds(const float* __restrict__ conds, float* __restrict__ dst) {
    int t = blockIdx.x * 256 + threadIdx.x;
    if (t < 512) dst[t] = conds[t];
}

// ---------------- launch ----------------
extern "C" void kernel_launch(void* const* d_in, const int* in_sizes, int n_in,
                              void* d_out, int out_size) {
    const float* nodes = (const float*)d_in[0];
    const float* edges = (const float*)d_in[1];
    const float* conds = (const float*)d_in[2];
    const float* Wqkv = (const float*)d_in[3];
    const float* bqkv = (const float*)d_in[4];
    const float* Wno = (const float*)d_in[5];
    const float* bno = (const float*)d_in[6];
    const float* Weo = (const float*)d_in[7];
    const float* beo = (const float*)d_in[8];
    const float* g1n = (const float*)d_in[9];
    const float* b1n = (const float*)d_in[10];
    const float* g1e = (const float*)d_in[11];
    const float* b1e = (const float*)d_in[12];
    const float* Wn1 = (const float*)d_in[13];
    const float* bn1 = (const float*)d_in[14];
    const float* Wn2 = (const float*)d_in[15];
    const float* bn2 = (const float*)d_in[16];
    const float* We1 = (const float*)d_in[17];
    const float* be1 = (const float*)d_in[18];
    const float* We2 = (const float*)d_in[19];
    const float* be2 = (const float*)d_in[20];
    const float* g2n = (const float*)d_in[21];
    const float* b2n = (const float*)d_in[22];
    const float* g2e = (const float*)d_in[23];
    const float* b2e = (const float*)d_in[24];

    float* out = (float*)d_out;
    float* out_nodes = out;
    float* out_edges = out + 131072;
    float* out_conds = out + 131072 + 33554432;

    cudaFuncSetAttribute(edge_tc, cudaFuncAttributeMaxDynamicSharedMemorySize, DSMEM);

    prep_kernel<<<1024, 256>>>(Weo, We1, We2);
    qkv_kernel<<<512, 256>>>(nodes, conds, Wqkv, bqkv);
    edge_tc<<<2048, 256, DSMEM>>>(edges, beo, g1e, b1e, be1, be2, g2e, b2e, out_edges);
    attn_kernel<<<512, 256>>>(nodes, Wno, bno, g1n, b1n);
    nodemlp_kernel<<<512, 256>>>(Wn1, bn1, Wn2, bn2, g2n, b2n, out_nodes);
    copy_conds<<<2, 256>>>(conds, out_conds);
}

// round 9
// speedup vs baseline: 1.5033x; 1.1632x over previous
#include <cuda_runtime.h>
#include <cuda_bf16.h>
#include <mma.h>
#include <cstdint>
#include <cstddef>

using namespace nvcuda;

#define SCALE 0.0625f
#define EPSLN 1e-5f

// edge_tc smem byte offsets (R6 layout)
#define OFF_A1H 0
#define OFF_A1L 33792
#define OFF_HH 67584
#define OFF_HL 101376
#define OFF_BH 135168
#define OFF_BL 172032
#define DSMEM 208896
#define LDA 264  // bf16 elems/row, A and H tiles (64 rows)
#define LDB 72   // bf16 elems/row, B stage (256 rows x 64 k + pad)
#define LDC 260  // f32 elems/row, C stage (aliases B at OFF_BH)

typedef wmma::fragment<wmma::matrix_a, 16, 16, 16, __nv_bfloat16, wmma::row_major> FragA;
typedef wmma::fragment<wmma::matrix_b, 16, 16, 16, __nv_bfloat16, wmma::col_major> FragB;
typedef wmma::fragment<wmma::accumulator, 16, 16, 16, float> FragC;

// ---------------- device scratch ----------------
__device__ float d_q[131072];
__device__ float d_k[131072];
__device__ float d_v[131072];
__device__ float d_an1[131072];
__device__ float d_logits[1048576];                        // (bi*8+h)*256 + j
__device__ unsigned short g_WeoH[65536], g_WeoL[65536];    // [256 n][256 k] row-major
__device__ unsigned short g_We1H[262144], g_We1L[262144];  // [1024][256]
__device__ unsigned short g_We2H[262144], g_We2L[262144];  // [256][1024]

__device__ __forceinline__ void split_w(float v, unsigned short* h, unsigned short* l) {
    __nv_bfloat16 hb = __float2bfloat16(v);
    *h = __bfloat16_as_ushort(hb);
    *l = __bfloat16_as_ushort(__float2bfloat16(v - __bfloat162float(hb)));
}
__device__ __forceinline__ void split_sm(char* smp, int off, int r, int c, float v) {
    __nv_bfloat16 hb = __float2bfloat16(v);
    *(unsigned short*)(smp + off + (r * LDA + c) * 2) = __bfloat16_as_ushort(hb);
    *(unsigned short*)(smp + off + 33792 + (r * LDA + c) * 2) =
        __bfloat16_as_ushort(__float2bfloat16(v - __bfloat162float(hb)));
}

// ---------------- prep: edge-weight bf16 hi/lo split (row-major) ----------------
__global__ void prep_kernel(const float* __restrict__ Weo, const float* __restrict__ We1,
                            const float* __restrict__ We2) {
    int idx = blockIdx.x * 256 + threadIdx.x;  // 262144
    if (idx < 65536) split_w(Weo[idx], &g_WeoH[idx], &g_WeoL[idx]);
    split_w(We1[idx], &g_We1H[idx], &g_We1L[idx]);
    split_w(We2[idx], &g_We2H[idx], &g_We2L[idx]);
}

// ---------------- qkv projection (row-major weights, float4) ----------------
__global__ void __launch_bounds__(256) qkv_kernel(const float* __restrict__ nodes,
                                                  const float* __restrict__ conds,
                                                  const float* __restrict__ Wqkv,
                                                  const float* __restrict__ bqkv) {
    __shared__ float x[256];
    int bi = blockIdx.x, b = bi >> 8, t = threadIdx.x;
    x[t] = nodes[bi * 256 + t] + conds[(b << 8) + t];
    __syncthreads();
    const float4* x4 = (const float4*)x;
#pragma unroll
    for (int s = 0; s < 3; s++) {
        int o = t + (s << 8);
        const float4* wr = (const float4*)(Wqkv + o * 256);
        float acc = bqkv[o];
#pragma unroll 8
        for (int c = 0; c < 64; c++) {
            float4 w = wr[c], xv = x4[c];
            acc += w.x * xv.x + w.y * xv.y + w.z * xv.z + w.w * xv.w;
        }
        float* dst = (s == 0) ? d_q : (s == 1) ? d_k : d_v;
        dst[bi * 256 + t] = acc;
    }
}

// ---------------- attn: precomputed logits -> softmax -> WV -> Wno -> LN1 ----------------
__global__ void __launch_bounds__(256) attn_kernel(const float* __restrict__ nodes,
                                                   const float* __restrict__ Wno,
                                                   const float* __restrict__ bno,
                                                   const float* __restrict__ g1n,
                                                   const float* __restrict__ b1n) {
    __shared__ float lg[8 * 256];
    __shared__ float wv[256];
    __shared__ float red[20];
    int bi = blockIdx.x, b = bi >> 8, t = threadIdx.x, w = t >> 5, lane = t & 31;
    {
        const float* lrow = d_logits + ((size_t)bi * 8 + w) * 256;
        float m = -1e30f;
        for (int j = lane; j < 256; j += 32) {
            float v = lrow[j];
            lg[w * 256 + j] = v;
            m = fmaxf(m, v);
        }
#pragma unroll
        for (int off = 16; off; off >>= 1) m = fmaxf(m, __shfl_xor_sync(0xffffffffu, m, off));
        float s = 0.f;
        for (int j = lane; j < 256; j += 32) {
            float e = __expf(lg[w * 256 + j] - m);
            lg[w * 256 + j] = e; s += e;
        }
#pragma unroll
        for (int off = 16; off; off >>= 1) s += __shfl_xor_sync(0xffffffffu, s, off);
        float inv = 1.f / s;
        for (int j = lane; j < 256; j += 32) lg[w * 256 + j] *= inv;
    }
    __syncthreads();
    const float* vb = d_v + b * 65536;
    float acc = 0.f;
#pragma unroll 4
    for (int j = 0; j < 256; j++) acc += lg[w * 256 + j] * vb[j * 256 + t];
    wv[t] = acc;
    __syncthreads();
    float a = bno[t];
    {
        const float4* wr = (const float4*)(Wno + t * 256);
        const float4* wv4 = (const float4*)wv;
#pragma unroll 8
        for (int c = 0; c < 64; c++) {
            float4 ww = wr[c], xv = wv4[c];
            a += ww.x * xv.x + ww.y * xv.y + ww.z * xv.z + ww.w * xv.w;
        }
    }
    a += nodes[bi * 256 + t];
    float s1 = a, s2 = a * a;
#pragma unroll
    for (int off = 16; off; off >>= 1) {
        s1 += __shfl_xor_sync(0xffffffffu, s1, off);
        s2 += __shfl_xor_sync(0xffffffffu, s2, off);
    }
    if (lane == 0) { red[w] = s1; red[8 + w] = s2; }
    __syncthreads();
    if (t == 0) {
        float a1 = 0.f, a2 = 0.f;
        for (int x = 0; x < 8; x++) { a1 += red[x]; a2 += red[8 + x]; }
        float m = a1 * (1.f / 256.f);
        red[16] = m;
        red[17] = rsqrtf(a2 * (1.f / 256.f) - m * m + EPSLN);
    }
    __syncthreads();
    d_an1[bi * 256 + t] = (a - red[16]) * red[17] * g1n[t] + b1n[t];
}

// ---------------- node MLP (row-major weights, float4) ----------------
__global__ void __launch_bounds__(256) nodemlp_kernel(const float* __restrict__ Wn1,
                                                      const float* __restrict__ bn1,
                                                      const float* __restrict__ Wn2,
                                                      const float* __restrict__ bn2,
                                                      const float* __restrict__ g2n,
                                                      const float* __restrict__ b2n,
                                                      float* __restrict__ out_nodes) {
    __shared__ float a[256];
    __shared__ float h[1024];
    __shared__ float red[20];
    int bi = blockIdx.x, t = threadIdx.x, w = t >> 5, lane = t & 31;
    a[t] = d_an1[bi * 256 + t];
    __syncthreads();
    const float4* a4 = (const float4*)a;
#pragma unroll
    for (int s = 0; s < 4; s++) {
        int m = t + (s << 8);
        const float4* wr = (const float4*)(Wn1 + m * 256);
        float acc = bn1[m];
#pragma unroll 8
        for (int c = 0; c < 64; c++) {
            float4 ww = wr[c], xv = a4[c];
            acc += ww.x * xv.x + ww.y * xv.y + ww.z * xv.z + ww.w * xv.w;
        }
        h[m] = fmaxf(acc, 0.f);
    }
    __syncthreads();
    float o = bn2[t];
    {
        const float4* wr = (const float4*)(Wn2 + t * 1024);
        const float4* h4 = (const float4*)h;
#pragma unroll 8
        for (int c = 0; c < 256; c++) {
            float4 ww = wr[c], xv = h4[c];
            o += ww.x * xv.x + ww.y * xv.y + ww.z * xv.z + ww.w * xv.w;
        }
    }
    float v = o + a[t];
    float s1 = v, s2 = v * v;
#pragma unroll
    for (int off = 16; off; off >>= 1) {
        s1 += __shfl_xor_sync(0xffffffffu, s1, off);
        s2 += __shfl_xor_sync(0xffffffffu, s2, off);
    }
    if (lane == 0) { red[w] = s1; red[8 + w] = s2; }
    __syncthreads();
    if (t == 0) {
        float a1 = 0.f, a2 = 0.f;
        for (int x = 0; x < 8; x++) { a1 += red[x]; a2 += red[8 + x]; }
        float m = a1 * (1.f / 256.f);
        red[16] = m;
        red[17] = rsqrtf(a2 * (1.f / 256.f) - m * m + EPSLN);
    }
    __syncthreads();
    out_nodes[bi * 256 + t] = (v - red[16]) * red[17] * g2n[t] + b2n[t];
}

// ---------------- edge pipeline: split-bf16 WMMA, R6 staging structure ----------------
__device__ __forceinline__ void stageB(char* smp, const unsigned short* __restrict__ WH,
                                       const unsigned short* __restrict__ WL, int wp,
                                       int kbase, int t) {
#pragma unroll
    for (int i = 0; i < 8; i++) {
        int idx = t + i * 256;
        int row = idx >> 3, seg = idx & 7;
        *((uint4*)(smp + OFF_BH + row * 144) + seg) =
            *((const uint4*)(WH + (size_t)row * wp + kbase) + seg);
        *((uint4*)(smp + OFF_BL + row * 144) + seg) =
            *((const uint4*)(WL + (size_t)row * wp + kbase) + seg);
    }
}

__device__ __forceinline__ void mma_chunk(const char* smp, int aoff, FragC acc[2][4],
                                          int mg, int ng, int kc) {
    const __nv_bfloat16* Ahi = (const __nv_bfloat16*)(smp + aoff);
    const __nv_bfloat16* Alo = (const __nv_bfloat16*)(smp + aoff + 33792);
    const __nv_bfloat16* Bhi = (const __nv_bfloat16*)(smp + OFF_BH);
    const __nv_bfloat16* Blo = (const __nv_bfloat16*)(smp + OFF_BL);
#pragma unroll
    for (int ks = 0; ks < 4; ks++) {
        int col = kc * 64 + ks * 16;
        FragA ah[2], al[2];
#pragma unroll
        for (int mi = 0; mi < 2; mi++) {
            int row0 = mg * 32 + mi * 16;
            wmma::load_matrix_sync(ah[mi], Ahi + row0 * LDA + col, LDA);
            wmma::load_matrix_sync(al[mi], Alo + row0 * LDA + col, LDA);
        }
#pragma unroll
        for (int ns = 0; ns < 4; ns++) {
            int n0 = ng * 64 + ns * 16;
            FragB bh, bl;
            wmma::load_matrix_sync(bh, Bhi + n0 * LDB + ks * 16, LDB);
            wmma::load_matrix_sync(bl, Blo + n0 * LDB + ks * 16, LDB);
#pragma unroll
            for (int mi = 0; mi < 2; mi++) {
                wmma::mma_sync(acc[mi][ns], ah[mi], bh, acc[mi][ns]);
                wmma::mma_sync(acc[mi][ns], ah[mi], bl, acc[mi][ns]);
                wmma::mma_sync(acc[mi][ns], al[mi], bh, acc[mi][ns]);
            }
        }
    }
}

__device__ __forceinline__ void storeC(char* smp, FragC acc[2][4], int mg, int ng) {
    float* C = (float*)(smp + OFF_BH);
#pragma unroll
    for (int mi = 0; mi < 2; mi++)
#pragma unroll
        for (int ns = 0; ns < 4; ns++)
            wmma::store_matrix_sync(C + (mg * 32 + mi * 16) * LDC + ng * 64 + ns * 16,
                                    acc[mi][ns], LDC, wmma::mem_row_major);
}

__global__ void __launch_bounds__(256) edge_tc(const float* __restrict__ edges,
                                               const float* __restrict__ beo,
                                               const float* __restrict__ g1e,
                                               const float* __restrict__ b1e,
                                               const float* __restrict__ be1,
                                               const float* __restrict__ be2,
                                               const float* __restrict__ g2e,
                                               const float* __restrict__ b2e,
                                               float* __restrict__ out_edges) {
    extern __shared__ char smp[];
    const int t = threadIdx.x, w = t >> 5, lane = t & 31;
    const int blk = blockIdx.x;   // 0..2047, 64 edge rows each
    const int bi = blk >> 2;
    const int b = bi >> 8;
    const int j0 = (blk & 3) << 6;
    const size_t rowbase = (size_t)blk * 64;
    const int r = t >> 2, sub = t & 3;  // epilogue: 4 threads per row
    const int MG = w >> 2, NG = w & 3;  // warp tile: 32 rows x 64 cols
    float* Cst = (float*)(smp + OFF_BH);

    // ---- T = q*k*scale + e -> split A1 tiles; fused per-head logits ----
    {
        float qv = d_q[bi * 256 + t] * SCALE;
        const float* ebase = edges + rowbase * 256 + t;
        const float* kbase = d_k + ((size_t)(b << 8) + j0) * 256 + t;
        float* lbase = d_logits + ((size_t)bi * 8 + w) * 256 + j0;
#pragma unroll 4
        for (int i = 0; i < 64; i++) {
            float v = qv * kbase[i * 256] + ebase[i * 256];
            split_sm(smp, OFF_A1H, i, t, v);
            float s = v;
#pragma unroll
            for (int off = 16; off; off >>= 1) s += __shfl_xor_sync(0xffffffffu, s, off);
            if (lane == 0) lbase[i] = s;
        }
    }

    // ---- G1: C = T @ Weo^T ----
    FragC acc1[2][4];
#pragma unroll
    for (int mi = 0; mi < 2; mi++)
#pragma unroll
        for (int ns = 0; ns < 4; ns++) wmma::fill_fragment(acc1[mi][ns], 0.f);
    for (int kc = 0; kc < 4; kc++) {
        __syncthreads();
        stageB(smp, g_WeoH, g_WeoL, 256, kc * 64, t);
        __syncthreads();
        mma_chunk(smp, OFF_A1H, acc1, MG, NG, kc);
    }
    __syncthreads();
    storeC(smp, acc1, MG, NG);
    __syncthreads();

    // ---- Epi1: v = relu(C+beo)+e ; LN -> A1 ----
    {
        float s1 = 0.f, s2 = 0.f;
        const float* erow = edges + (rowbase + r) * 256;
        float* Crow = Cst + r * LDC;
#pragma unroll 4
        for (int i = 0; i < 64; i++) {
            int c = sub * 64 + i;
            float v = fmaxf(Crow[c] + beo[c], 0.f) + erow[c];
            Crow[c] = v; s1 += v; s2 += v * v;
        }
        s1 += __shfl_xor_sync(0xffffffffu, s1, 1); s2 += __shfl_xor_sync(0xffffffffu, s2, 1);
        s1 += __shfl_xor_sync(0xffffffffu, s1, 2); s2 += __shfl_xor_sync(0xffffffffu, s2, 2);
        float m = s1 * (1.f / 256.f);
        float rs = rsqrtf(s2 * (1.f / 256.f) - m * m + EPSLN);
#pragma unroll 4
        for (int i = 0; i < 64; i++) {
            int c = sub * 64 + i;
            split_sm(smp, OFF_A1H, r, c, (Crow[c] - m) * rs * g1e[c] + b1e[c]);
        }
    }

    // ---- MLP: 4 hidden chunks: G2 -> relu -> G3 accumulate ----
    FragC acc3[2][4];
#pragma unroll
    for (int mi = 0; mi < 2; mi++)
#pragma unroll
        for (int ns = 0; ns < 4; ns++) wmma::fill_fragment(acc3[mi][ns], 0.f);

#pragma unroll 1
    for (int nc = 0; nc < 4; nc++) {
        FragC acc2[2][4];
#pragma unroll
        for (int mi = 0; mi < 2; mi++)
#pragma unroll
            for (int ns = 0; ns < 4; ns++) wmma::fill_fragment(acc2[mi][ns], 0.f);
        for (int kc = 0; kc < 4; kc++) {
            __syncthreads();
            stageB(smp, g_We1H + nc * 65536, g_We1L + nc * 65536, 256, kc * 64, t);
            __syncthreads();
            mma_chunk(smp, OFF_A1H, acc2, MG, NG, kc);
        }
        __syncthreads();
        storeC(smp, acc2, MG, NG);
        __syncthreads();
        {   // Epi-H: H = relu(C + be1)
            float* Crow = Cst + r * LDC;
#pragma unroll 4
            for (int i = 0; i < 64; i++) {
                int c = sub * 64 + i;
                split_sm(smp, OFF_HH, r, c, fmaxf(Crow[c] + be1[nc * 256 + c], 0.f));
            }
        }
        for (int kc = 0; kc < 4; kc++) {
            __syncthreads();
            stageB(smp, g_We2H, g_We2L, 1024, nc * 256 + kc * 64, t);
            __syncthreads();
            mma_chunk(smp, OFF_HH, acc3, MG, NG, kc);
        }
    }
    __syncthreads();
    storeC(smp, acc3, MG, NG);
    __syncthreads();

    // ---- Epi3: v = C + be2 + A1 ; LN -> out ----
    {
        float s1 = 0.f, s2 = 0.f;
        float* Crow = Cst + r * LDC;
        const unsigned short* a1h = (const unsigned short*)(smp + OFF_A1H) + r * LDA;
        const unsigned short* a1l = (const unsigned short*)(smp + OFF_A1L) + r * LDA;
#pragma unroll 4
        for (int i = 0; i < 64; i++) {
            int c = sub * 64 + i;
            float a1 = __bfloat162float(__ushort_as_bfloat16(a1h[c])) +
                       __bfloat162float(__ushort_as_bfloat16(a1l[c]));
            float v = Crow[c] + be2[c] + a1;
            Crow[c] = v; s1 += v; s2 += v * v;
        }
        s1 += __shfl_xor_sync(0xffffffffu, s1, 1); s2 += __shfl_xor_sync(0xffffffffu, s2, 1);
        s1 += __shfl_xor_sync(0xffffffffu, s1, 2); s2 += __shfl_xor_sync(0xffffffffu, s2, 2);
        float m = s1 * (1.f / 256.f);
        float rs = rsqrtf(s2 * (1.f / 256.f) - m * m + EPSLN);
        float* orow = out_edges + (rowbase + r) * 256;
#pragma unroll 4
        for (int i = 0; i < 64; i++) {
            int c = sub * 64 + i;
            orow[c] = (Crow[c] - m) * rs * g2e[c] + b2e[c];
        }
    }
}

__global__ void copy_conds(const float* __restrict__ conds, float* __restrict__ dst) {
    int t = blockIdx.x * 256 + threadIdx.x;
    if (t < 512) dst[t] = conds[t];
}

// ---------------- launch ----------------
extern "C" void kernel_launch(void* const* d_in, const int* in_sizes, int n_in,
                              void* d_out, int out_size) {
    const float* nodes = (const float*)d_in[0];
    const float* edges = (const float*)d_in[1];
    const float* conds = (const float*)d_in[2];
    const float* Wqkv = (const float*)d_in[3];
    const float* bqkv = (const float*)d_in[4];
    const float* Wno = (const float*)d_in[5];
    const float* bno = (const float*)d_in[6];
    const float* Weo = (const float*)d_in[7];
    const float* beo = (const float*)d_in[8];
    const float* g1n = (const float*)d_in[9];
    const float* b1n = (const float*)d_in[10];
    const float* g1e = (const float*)d_in[11];
    const float* b1e = (const float*)d_in[12];
    const float* Wn1 = (const float*)d_in[13];
    const float* bn1 = (const float*)d_in[14];
    const float* Wn2 = (const float*)d_in[15];
    const float* bn2 = (const float*)d_in[16];
    const float* We1 = (const float*)d_in[17];
    const float* be1 = (const float*)d_in[18];
    const float* We2 = (const float*)d_in[19];
    const float* be2 = (const float*)d_in[20];
    const float* g2n = (const float*)d_in[21];
    const float* b2n = (const float*)d_in[22];
    const float* g2e = (const float*)d_in[23];
    const float* b2e = (const float*)d_in[24];

    float* out = (float*)d_out;
    float* out_nodes = out;
    float* out_edges = out + 131072;
    float* out_conds = out + 131072 + 33554432;

    cudaFuncSetAttribute(edge_tc, cudaFuncAttributeMaxDynamicSharedMemorySize, DSMEM);

    prep_kernel<<<1024, 256>>>(Weo, We1, We2);
    qkv_kernel<<<512, 256>>>(nodes, conds, Wqkv, bqkv);
    edge_tc<<<2048, 256, DSMEM>>>(edges, beo, g1e, b1e, be1, be2, g2e, b2e, out_edges);
    attn_kernel<<<512, 256>>>(nodes, Wno, bno, g1n, b1n);
    nodemlp_kernel<<<512, 256>>>(Wn1, bn1, Wn2, bn2, g2n, b2n, out_nodes);
    copy_conds<<<2, 256>>>(conds, out_conds);
}